// round 1
// baseline (speedup 1.0000x reference)
#include <cuda_runtime.h>

// Problem constants
#define F_IN   64
#define F_OUT  64
#define IRREP  1771
#define NGRID  512
#define BATCH  256
#define RSTRIDE (F_OUT * IRREP)   // 113344 ; also F_IN*IRREP for x rows

// Scratch for psi (f_in*f_out, IRREP) = 4096 x 1771 fp32 (~29 MB), static device global
__device__ float g_psi[4096 * IRREP];

// blocks per l = 4*d*d ; cumulative
__constant__ int c_cum[12] = {0, 4, 40, 140, 336, 660, 1144, 1820, 2720, 3876, 5320, 7084};
// irrep block offsets: cumsum of d^2
__constant__ int c_off[11] = {0, 1, 10, 35, 84, 165, 286, 455, 680, 969, 1330};

// ---------------------------------------------------------------------------
// Kernel 1: psi[r, c] = (1/sqrt(512)) * sum_n W[r*512 + n] * D[n*1771 + c]
// r = i*64 + o  (w is (f_in, f_out, n_grid) row-major), c = irrep index.
// 64x64 tile, BK=16, 256 threads, 4x4 microtile.
// ---------------------------------------------------------------------------
__global__ __launch_bounds__(256) void psi_kernel(const float* __restrict__ W,
                                                  const float* __restrict__ D) {
    __shared__ float As[16 * 68];   // [k][row], padded stride 68
    __shared__ float Bs[16 * 68];   // [k][col]

    const int tid   = threadIdx.x;
    const int tileN = blockIdx.x;   // 0..27
    const int tileM = blockIdx.y;   // 0..63

    // load mappings
    const int lk16 = tid & 15;      // A: k column
    const int lr16 = tid >> 4;      // A: row (16 rows, x4)
    const int lcol = tid & 63;      // B: col
    const int lk4  = tid >> 6;      // B: k row (4, x4)
    const int gcolb = tileN * 64 + lcol;

    const float* wbase = W + (tileM * 64 + lr16) * NGRID + lk16;

    // compute mapping
    const int tx = tid & 15;
    const int ty = tid >> 4;

    float acc[4][4] = {};

    for (int kt = 0; kt < NGRID; kt += 16) {
#pragma unroll
        for (int j = 0; j < 4; j++) {
            As[lk16 * 68 + lr16 + 16 * j] = wbase[(16 * j) * NGRID + kt];
        }
#pragma unroll
        for (int j = 0; j < 4; j++) {
            const int krow = lk4 + 4 * j;
            Bs[krow * 68 + lcol] = (gcolb < IRREP) ? D[(kt + krow) * IRREP + gcolb] : 0.0f;
        }
        __syncthreads();

#pragma unroll
        for (int kk = 0; kk < 16; kk++) {
            const float4 av = *(const float4*)&As[kk * 68 + ty * 4];
            const float4 bv = *(const float4*)&Bs[kk * 68 + tx * 4];
            const float aarr[4] = {av.x, av.y, av.z, av.w};
            const float barr[4] = {bv.x, bv.y, bv.z, bv.w};
#pragma unroll
            for (int ii = 0; ii < 4; ii++)
#pragma unroll
                for (int jj = 0; jj < 4; jj++)
                    acc[ii][jj] = fmaf(aarr[ii], barr[jj], acc[ii][jj]);
        }
        __syncthreads();
    }

    const float scale = 0.04419417382415922f;  // 1/sqrt(512)
#pragma unroll
    for (int rr = 0; rr < 4; rr++) {
        const int grow = tileM * 64 + ty * 4 + rr;
#pragma unroll
        for (int cc = 0; cc < 4; cc++) {
            const int gcol = tileN * 64 + tx * 4 + cc;
            if (gcol < IRREP) g_psi[grow * IRREP + gcol] = acc[rr][cc] * scale;
        }
    }
}

// ---------------------------------------------------------------------------
// Kernel 2: per-l GEMM  out[(b,m),(o,v)] = alpha_l * sum_{(i,u)} x * psi
//   M = 256*d (b-major, m-minor), N = 64*d (o-major, v-minor), K = 64*d (i-major, u-minor)
//   All dims divisible by tile sizes -> no bounds checks.
//   x   addr: b*113344 + i*1771 + off + u*d + m
//   psi addr: i*113344 + o*1771 + off + u*d + v
//   out addr: b*113344 + o*1771 + off + v*d + m
// Flat grid of 7084 blocks covers all l. 64x64 tile, BK=16, 256 threads, 4x4/thread.
// ---------------------------------------------------------------------------
__global__ __launch_bounds__(256) void so3_kernel(const float* __restrict__ X,
                                                  float* __restrict__ O) {
    __shared__ float As[16 * 68];
    __shared__ float Bs[16 * 68];
    __shared__ int   ka[64 * 21];   // k -> i*1771  + u*d  (max Kl = 1344)
    __shared__ int   kb[64 * 21];   // k -> i*113344 + u*d

    const int bid = blockIdx.x;
    int l = 0;
    while (bid >= c_cum[l + 1]) ++l;
    const int d    = 2 * l + 1;
    const int off  = c_off[l];
    const int loc  = bid - c_cum[l];
    const int tileM = loc / d;           // 0 .. 4d-1
    const int tileN = loc - tileM * d;   // 0 .. d-1
    const int Kl   = 64 * d;

    const int tid = threadIdx.x;

    // Precompute per-k offsets (amortized divmods)
    for (int kk = tid; kk < Kl; kk += 256) {
        const int i = kk / d;
        const int u = kk - i * d;
        ka[kk] = i * IRREP   + u * d;
        kb[kk] = i * RSTRIDE + u * d;
    }

    // Per-thread load bases (divmod once)
    const int lrow = tid & 63;    // row for A loads / col for B loads
    const int lk   = tid >> 6;    // k sub-row (4, x4)

    const int ra = tileM * 64 + lrow;        // global A row = (b, m)
    const int ba = ra / d;
    const int ma = ra - ba * d;
    const float* Abase = X + ba * RSTRIDE + off + ma;

    const int cb = tileN * 64 + lrow;        // global B col = (o, v)
    const int ob = cb / d;
    const int vb = cb - ob * d;
    const float* Bbase = g_psi + ob * IRREP + off + vb;

    __syncthreads();  // ka/kb visible

    const int tx = tid & 15;
    const int ty = tid >> 4;
    float acc[4][4] = {};

    for (int kt = 0; kt < Kl; kt += 16) {
#pragma unroll
        for (int j = 0; j < 4; j++) {
            const int krow = lk + 4 * j;
            As[krow * 68 + lrow] = Abase[ka[kt + krow]];
            Bs[krow * 68 + lrow] = Bbase[kb[kt + krow]];
        }
        __syncthreads();

#pragma unroll
        for (int kk = 0; kk < 16; kk++) {
            const float4 av = *(const float4*)&As[kk * 68 + ty * 4];
            const float4 bv = *(const float4*)&Bs[kk * 68 + tx * 4];
            const float aarr[4] = {av.x, av.y, av.z, av.w};
            const float barr[4] = {bv.x, bv.y, bv.z, bv.w};
#pragma unroll
            for (int ii = 0; ii < 4; ii++)
#pragma unroll
                for (int jj = 0; jj < 4; jj++)
                    acc[ii][jj] = fmaf(aarr[ii], barr[jj], acc[ii][jj]);
        }
        __syncthreads();
    }

    const float alpha = rsqrtf(64.0f * (float)d);  // 1/sqrt(f_in * d)
#pragma unroll
    for (int rr = 0; rr < 4; rr++) {
        const int r = tileM * 64 + ty * 4 + rr;
        const int b = r / d;
        const int m = r - b * d;
        float* orow = O + b * RSTRIDE + off + m;
#pragma unroll
        for (int cc = 0; cc < 4; cc++) {
            const int c = tileN * 64 + tx * 4 + cc;
            const int o = c / d;
            const int v = c - o * d;
            orow[o * IRREP + v * d] = acc[rr][cc] * alpha;
        }
    }
}

// ---------------------------------------------------------------------------
// Launch: inputs in metadata order: x (256,64,1771) f32, D (512,1771) f32,
// w (64,64,512) f32. Output (256,64,1771) f32.
// ---------------------------------------------------------------------------
extern "C" void kernel_launch(void* const* d_in, const int* in_sizes, int n_in,
                              void* d_out, int out_size) {
    const float* x = (const float*)d_in[0];
    const float* D = (const float*)d_in[1];
    const float* w = (const float*)d_in[2];
    float* out = (float*)d_out;

    psi_kernel<<<dim3(28, 64), 256>>>(w, D);   // writes g_psi
    so3_kernel<<<7084, 256>>>(x, out);
}

// round 2
// speedup vs baseline: 1.5243x; 1.5243x over previous
#include <cuda_runtime.h>

// Problem constants
#define F_IN   64
#define F_OUT  64
#define IRREP  1771
#define NGRID  512
#define BATCH  256
#define RSTRIDE (F_OUT * IRREP)   // 113344 ; also F_IN*IRREP for x rows

// Scratch for psi (f_in*f_out, IRREP) = 4096 x 1771 fp32 (~29 MB)
__device__ float g_psi[4096 * IRREP];

// stage-2 blocks per l = 2*d*d ; cumulative (tile 128x64)
__constant__ int c_cum2[12] = {0, 2, 20, 70, 168, 330, 572, 910, 1360, 1938, 2660, 3542};
// irrep block offsets: cumsum of d^2
__constant__ int c_off[11] = {0, 1, 10, 35, 84, 165, 286, 455, 680, 969, 1330};

// ---------------------------------------------------------------------------
// Kernel 1: psi[r, c] = (1/sqrt(512)) * sum_n W[r*512 + n] * D[n*1771 + c]
// (unchanged from R1 — ~8% of runtime)
// ---------------------------------------------------------------------------
__global__ __launch_bounds__(256) void psi_kernel(const float* __restrict__ W,
                                                  const float* __restrict__ D) {
    __shared__ float As[16 * 68];
    __shared__ float Bs[16 * 68];

    const int tid   = threadIdx.x;
    const int tileN = blockIdx.x;   // 0..27
    const int tileM = blockIdx.y;   // 0..63

    const int lk16 = tid & 15;
    const int lr16 = tid >> 4;
    const int lcol = tid & 63;
    const int lk4  = tid >> 6;
    const int gcolb = tileN * 64 + lcol;

    const float* wbase = W + (tileM * 64 + lr16) * NGRID + lk16;

    const int tx = tid & 15;
    const int ty = tid >> 4;

    float acc[4][4] = {};

    for (int kt = 0; kt < NGRID; kt += 16) {
#pragma unroll
        for (int j = 0; j < 4; j++) {
            As[lk16 * 68 + lr16 + 16 * j] = wbase[(16 * j) * NGRID + kt];
        }
#pragma unroll
        for (int j = 0; j < 4; j++) {
            const int krow = lk4 + 4 * j;
            Bs[krow * 68 + lcol] = (gcolb < IRREP) ? D[(kt + krow) * IRREP + gcolb] : 0.0f;
        }
        __syncthreads();

#pragma unroll
        for (int kk = 0; kk < 16; kk++) {
            const float4 av = *(const float4*)&As[kk * 68 + ty * 4];
            const float4 bv = *(const float4*)&Bs[kk * 68 + tx * 4];
            const float aarr[4] = {av.x, av.y, av.z, av.w};
            const float barr[4] = {bv.x, bv.y, bv.z, bv.w};
#pragma unroll
            for (int ii = 0; ii < 4; ii++)
#pragma unroll
                for (int jj = 0; jj < 4; jj++)
                    acc[ii][jj] = fmaf(aarr[ii], barr[jj], acc[ii][jj]);
        }
        __syncthreads();
    }

    const float scale = 0.04419417382415922f;  // 1/sqrt(512)
#pragma unroll
    for (int rr = 0; rr < 4; rr++) {
        const int grow = tileM * 64 + ty * 4 + rr;
#pragma unroll
        for (int cc = 0; cc < 4; cc++) {
            const int gcol = tileN * 64 + tx * 4 + cc;
            if (gcol < IRREP) g_psi[grow * IRREP + gcol] = acc[rr][cc] * scale;
        }
    }
}

// ---------------------------------------------------------------------------
// Kernel 2: per-l GEMM, 128x64 CTA tile, BK=16, 256 threads, 8x4 microtile,
// double-buffered smem (1 syncthreads per k-tile), reversed block order.
//   M = 256*d (b-major, m-minor), N = 64*d (o-major, v-minor), K = 64*d (i,u)
//   x   addr: b*113344 + i*1771   + off + u*d + m
//   psi addr: i*113344 + o*1771   + off + u*d + v
//   out addr: b*113344 + o*1771   + off + v*d + m
// ---------------------------------------------------------------------------
__global__ __launch_bounds__(256) void so3_kernel(const float* __restrict__ X,
                                                  float* __restrict__ O) {
    __shared__ float As[2][16][128];   // [buf][k][row]
    __shared__ float Bs[2][16][64];    // [buf][k][col]
    __shared__ int   ka[64 * 21];      // k -> i*1771   + u*d   (max Kl = 1344)
    __shared__ int   kb[64 * 21];      // k -> i*113344 + u*d

    // reversed order: largest-l (longest) blocks run first
    const int bid = (int)gridDim.x - 1 - (int)blockIdx.x;
    int l = 0;
    while (bid >= c_cum2[l + 1]) ++l;
    const int d     = 2 * l + 1;
    const int off   = c_off[l];
    const int loc   = bid - c_cum2[l];
    const int tileM = loc / d;           // 0 .. 2d-1  (128-row tiles)
    const int tileN = loc - tileM * d;   // 0 .. d-1   (64-col tiles)
    const int Kl    = 64 * d;
    const int nIter = 4 * d;             // Kl / 16

    const int tid = threadIdx.x;

    // Precompute per-k offsets (amortized divmods)
    for (int kk = tid; kk < Kl; kk += 256) {
        const int i = kk / d;
        const int u = kk - i * d;
        ka[kk] = i * IRREP   + u * d;
        kb[kk] = i * RSTRIDE + u * d;
    }

    // Per-thread global-load bases (divmod once)
    const int lrowA = tid & 127;          // A row within tile
    const int lkA   = (tid >> 7) * 8;     // A k base (0 or 8), loads 8 krows
    const int ra = tileM * 128 + lrowA;
    const int ba = ra / d;
    const int ma = ra - ba * d;
    const float* Abase = X + ba * RSTRIDE + off + ma;

    const int lcolB = tid & 63;           // B col within tile
    const int lkB   = (tid >> 6) * 4;     // B k base (0,4,8,12), loads 4 krows
    const int cb = tileN * 64 + lcolB;
    const int ob = cb / d;
    const int vb = cb - ob * d;
    const float* Bbase = g_psi + ob * IRREP + off + vb;

    __syncthreads();  // ka/kb visible

    // Prologue: tile 0 -> buffer 0
    {
#pragma unroll
        for (int j = 0; j < 8; j++)
            As[0][lkA + j][lrowA] = Abase[ka[lkA + j]];
#pragma unroll
        for (int j = 0; j < 4; j++)
            Bs[0][lkB + j][lcolB] = Bbase[kb[lkB + j]];
    }
    __syncthreads();

    const int tx = tid & 15;              // 16 cols of 4
    const int ty = tid >> 4;              // 16 rows of 8
    float acc[8][4] = {};

    for (int it = 0; it < nIter; ++it) {
        const int cur = it & 1;

        // Prefetch next k-tile from global into registers
        float pa[8], pb[4];
        const bool more = (it + 1 < nIter);
        if (more) {
            const int kt2 = (it + 1) * 16;
#pragma unroll
            for (int j = 0; j < 8; j++) pa[j] = Abase[ka[kt2 + lkA + j]];
#pragma unroll
            for (int j = 0; j < 4; j++) pb[j] = Bbase[kb[kt2 + lkB + j]];
        }

        // Compute on current buffer
#pragma unroll
        for (int kk = 0; kk < 16; kk++) {
            const float4 a0 = *(const float4*)&As[cur][kk][ty * 8];
            const float4 a1 = *(const float4*)&As[cur][kk][ty * 8 + 4];
            const float4 bv = *(const float4*)&Bs[cur][kk][tx * 4];
            const float aarr[8] = {a0.x, a0.y, a0.z, a0.w, a1.x, a1.y, a1.z, a1.w};
            const float barr[4] = {bv.x, bv.y, bv.z, bv.w};
#pragma unroll
            for (int ii = 0; ii < 8; ii++)
#pragma unroll
                for (int jj = 0; jj < 4; jj++)
                    acc[ii][jj] = fmaf(aarr[ii], barr[jj], acc[ii][jj]);
        }

        // Store prefetched tile into the other buffer
        if (more) {
            const int nb = cur ^ 1;
#pragma unroll
            for (int j = 0; j < 8; j++) As[nb][lkA + j][lrowA] = pa[j];
#pragma unroll
            for (int j = 0; j < 4; j++) Bs[nb][lkB + j][lcolB] = pb[j];
        }
        __syncthreads();
    }

    const float alpha = rsqrtf(64.0f * (float)d);  // 1/sqrt(f_in * d)
#pragma unroll
    for (int rr = 0; rr < 8; rr++) {
        const int r = tileM * 128 + ty * 8 + rr;
        const int b = r / d;
        const int m = r - b * d;
        float* orow = O + b * RSTRIDE + off + m;
#pragma unroll
        for (int cc = 0; cc < 4; cc++) {
            const int c = tileN * 64 + tx * 4 + cc;
            const int o = c / d;
            const int v = c - o * d;
            orow[o * IRREP + v * d] = acc[rr][cc] * alpha;
        }
    }
}

// ---------------------------------------------------------------------------
// Launch: inputs: x (256,64,1771) f32, D (512,1771) f32, w (64,64,512) f32.
// Output (256,64,1771) f32.
// ---------------------------------------------------------------------------
extern "C" void kernel_launch(void* const* d_in, const int* in_sizes, int n_in,
                              void* d_out, int out_size) {
    const float* x = (const float*)d_in[0];
    const float* D = (const float*)d_in[1];
    const float* w = (const float*)d_in[2];
    float* out = (float*)d_out;

    psi_kernel<<<dim3(28, 64), 256>>>(w, D);   // writes g_psi
    so3_kernel<<<3542, 256>>>(x, out);
}

// round 5
// speedup vs baseline: 1.6788x; 1.1013x over previous
#include <cuda_runtime.h>
#include <cuda_bf16.h>
#include <cstdint>

// Problem constants
#define F_IN   64
#define F_OUT  64
#define IRREP  1771
#define NGRID  512
#define BATCH  256
#define RSTRIDE (F_OUT * IRREP)   // 113344

// bf16 hi/lo planes.
// A_l: rows r=(b*d+m) [256d], cols k=(i*d+u) [64d]; base elem = 16384*c_off[l]
// B_l: rows n=(o*d+v) [64d],  cols k=(i*d+u) [64d]; base elem =  4096*c_off[l]
#define AELEMS 29016064   // 16384*1771
#define BELEMS 7254016    // 4096*1771
__device__ __nv_bfloat16 g_Ahi[AELEMS];
__device__ __nv_bfloat16 g_Alo[AELEMS];
__device__ __nv_bfloat16 g_Bhi[BELEMS];
__device__ __nv_bfloat16 g_Blo[BELEMS];

// stage-2 blocks per l = 2*d*d (tile 128x64); cumulative
__constant__ int c_cum2[12] = {0, 2, 20, 70, 168, 330, 572, 910, 1360, 1938, 2660, 3542};
// cumsum of d^2 (12 entries so [l+1] is always valid)
__constant__ int c_off12[12] = {0, 1, 10, 35, 84, 165, 286, 455, 680, 969, 1330, 1771};

// ---------------------------------------------------------------------------
// helpers
// ---------------------------------------------------------------------------
__device__ __forceinline__ uint32_t smem_u32(const void* p) {
    uint32_t a;
    asm("{ .reg .u64 t; cvta.to.shared.u64 t, %1; cvt.u32.u64 %0, t; }" : "=r"(a) : "l"(p));
    return a;
}

__device__ __forceinline__ void cp16(uint32_t dst, const void* src) {
    asm volatile("cp.async.cg.shared.global [%0], [%1], 16;"
                 :: "r"(dst), "l"((uint64_t)__cvta_generic_to_global(src)) : "memory");
}
#define CP_COMMIT() asm volatile("cp.async.commit_group;" ::: "memory")
#define CP_WAIT2()  asm volatile("cp.async.wait_group 2;" ::: "memory")

#define LDSM_X4(r0, r1, r2, r3, addr) \
    asm volatile("ldmatrix.sync.aligned.m8n8.x4.shared.b16 {%0,%1,%2,%3}, [%4];" \
                 : "=r"(r0), "=r"(r1), "=r"(r2), "=r"(r3) : "r"(addr))

__device__ __forceinline__ void mma_bf16(float* c, const uint32_t* a, uint32_t b0, uint32_t b1) {
    asm volatile(
        "mma.sync.aligned.m16n8k16.row.col.f32.bf16.bf16.f32 "
        "{%0,%1,%2,%3}, {%4,%5,%6,%7}, {%8,%9}, {%0,%1,%2,%3};"
        : "+f"(c[0]), "+f"(c[1]), "+f"(c[2]), "+f"(c[3])
        : "r"(a[0]), "r"(a[1]), "r"(a[2]), "r"(a[3]), "r"(b0), "r"(b1));
}

__device__ __forceinline__ uint32_t packbf2(float a, float b) {
    uint16_t x = __bfloat16_as_ushort(__float2bfloat16(a));
    uint16_t y = __bfloat16_as_ushort(__float2bfloat16(b));
    return (uint32_t)x | ((uint32_t)y << 16);
}

// ---------------------------------------------------------------------------
// Kernel 0: xprep — x (B, F_IN, IRREP) f32 -> per-l bf16 hi/lo A planes.
// One CTA per (b, l). smem slab = x[b][:, off:off+d^2] (64*d^2 f32).
// ---------------------------------------------------------------------------
__global__ __launch_bounds__(256) void xprep_kernel(const float* __restrict__ X) {
    extern __shared__ float sm[];
    const int b = blockIdx.x;
    const int l = blockIdx.y;
    const int d  = 2 * l + 1;
    const int d2 = d * d;
    const int off = c_off12[l];
    const int Kl = 64 * d;
    const int tid = threadIdx.x;

    for (int i = 0; i < 64; i++)
        for (int j = tid; j < d2; j += 256)
            sm[i * d2 + j] = X[(size_t)b * RSTRIDE + i * IRREP + off + j];
    __syncthreads();

    const int Abase = 16384 * off;           // elem base of A_l
    const int total = 64 * d2;               // d rows x Kl cols for this b
    for (int idx = tid * 8; idx < total; idx += 256 * 8) {
        const int m  = idx / Kl;
        const int k0 = idx - m * Kl;
        uint32_t hi[4], lo[4];
#pragma unroll
        for (int p = 0; p < 4; p++) {
            float v[2], vl[2];
#pragma unroll
            for (int e = 0; e < 2; e++) {
                const int k = k0 + p * 2 + e;
                const int i = k / d;
                const int u = k - i * d;
                const float x = sm[i * d2 + u * d + m];
                const float xh = __bfloat162float(__float2bfloat16(x));
                v[e] = x;
                vl[e] = x - xh;
            }
            hi[p] = packbf2(v[0], v[1]);
            lo[p] = packbf2(vl[0], vl[1]);
        }
        const int o = Abase + (b * d + m) * Kl + k0;
        *(uint4*)(g_Ahi + o) = make_uint4(hi[0], hi[1], hi[2], hi[3]);
        *(uint4*)(g_Alo + o) = make_uint4(lo[0], lo[1], lo[2], lo[3]);
    }
}

// ---------------------------------------------------------------------------
// Kernel 1: psi GEMM (fp32 SIMT) -> scatter into bf16 hi/lo B planes.
// psi[r=(i*64+o)][c] = (1/sqrt(512)) * sum_n W[r][n] * D[n][c]
// B_l[(o*d+v)][(i*d+u)] with c = off + u*d + v.
// ---------------------------------------------------------------------------
__global__ __launch_bounds__(256) void psi_kernel(const float* __restrict__ W,
                                                  const float* __restrict__ D) {
    __shared__ float As[16 * 68];
    __shared__ float Bs[16 * 68];

    const int tid   = threadIdx.x;
    const int tileN = blockIdx.x;   // 0..27
    const int tileM = blockIdx.y;   // 0..63

    const int lk16 = tid & 15;
    const int lr16 = tid >> 4;
    const int lcol = tid & 63;
    const int lk4  = tid >> 6;
    const int gcolb = tileN * 64 + lcol;

    const float* wbase = W + (tileM * 64 + lr16) * NGRID + lk16;
    const int tx = tid & 15;
    const int ty = tid >> 4;
    float acc[4][4] = {};

    for (int kt = 0; kt < NGRID; kt += 16) {
#pragma unroll
        for (int j = 0; j < 4; j++)
            As[lk16 * 68 + lr16 + 16 * j] = wbase[(16 * j) * NGRID + kt];
#pragma unroll
        for (int j = 0; j < 4; j++) {
            const int krow = lk4 + 4 * j;
            Bs[krow * 68 + lcol] = (gcolb < IRREP) ? D[(kt + krow) * IRREP + gcolb] : 0.0f;
        }
        __syncthreads();
#pragma unroll
        for (int kk = 0; kk < 16; kk++) {
            const float4 av = *(const float4*)&As[kk * 68 + ty * 4];
            const float4 bv = *(const float4*)&Bs[kk * 68 + tx * 4];
            const float aarr[4] = {av.x, av.y, av.z, av.w};
            const float barr[4] = {bv.x, bv.y, bv.z, bv.w};
#pragma unroll
            for (int ii = 0; ii < 4; ii++)
#pragma unroll
                for (int jj = 0; jj < 4; jj++)
                    acc[ii][jj] = fmaf(aarr[ii], barr[jj], acc[ii][jj]);
        }
        __syncthreads();
    }

    const float scale = 0.04419417382415922f;  // 1/sqrt(512)
#pragma unroll
    for (int cc = 0; cc < 4; cc++) {
        const int gcol = tileN * 64 + tx * 4 + cc;
        if (gcol >= IRREP) continue;
        int l = 0;
        while (gcol >= c_off12[l + 1]) ++l;
        const int d   = 2 * l + 1;
        const int off = c_off12[l];
        const int rel = gcol - off;
        const int u = rel / d;
        const int v = rel - u * d;
        const int Bbase = 4096 * off;
        const int Kl = 64 * d;
#pragma unroll
        for (int rr = 0; rr < 4; rr++) {
            const int grow = tileM * 64 + ty * 4 + rr;
            const int i = grow >> 6;
            const int o = grow & 63;
            const float val = acc[rr][cc] * scale;
            const __nv_bfloat16 h = __float2bfloat16(val);
            const __nv_bfloat16 lw = __float2bfloat16(val - __bfloat162float(h));
            const int idx = Bbase + (o * d + v) * Kl + (i * d + u);
            g_Bhi[idx] = h;
            g_Blo[idx] = lw;
        }
    }
}

// ---------------------------------------------------------------------------
// Kernel 2: so3 GEMM per l via mma.sync bf16 (3-product split).
// CTA tile 128x64, K-chunk 32, 8 warps (4x2 of 32x32), 4-stage cp.async.
// smem per stage: A_hi 8K | A_lo 8K | B_hi 4K | B_lo 4K = 24KB.
// Swizzle: byte = row*64 + ((chunk ^ ((row>>1)&3))<<4), chunk = k/8.
// ---------------------------------------------------------------------------
#define STAGE_BYTES 24576
#define OFF_SA_HI 0
#define OFF_SA_LO 8192
#define OFF_SB_HI 16384
#define OFF_SB_LO 20480
#define SO3_SMEM (4 * STAGE_BYTES)

__global__ __launch_bounds__(256, 2) void so3_kernel(float* __restrict__ O) {
    extern __shared__ __align__(1024) char dsm[];
    __shared__ int colOff[64];
    const uint32_t sb = smem_u32(dsm);

    const int tid  = threadIdx.x;
    const int wid  = tid >> 5;
    const int lane = tid & 31;
    const int wm = wid >> 1;     // 0..3  (m tile of 32)
    const int wn = wid & 1;      // 0..1  (n tile of 32)

    // tile mapping (reversed: largest l first)
    const int bid = (int)gridDim.x - 1 - (int)blockIdx.x;
    int l = 0;
    while (bid >= c_cum2[l + 1]) ++l;
    const int d     = 2 * l + 1;
    const int off   = c_off12[l];
    const int loc   = bid - c_cum2[l];
    const int tileM = loc / d;
    const int tileN = loc - tileM * d;
    const int Kl    = 64 * d;
    const int nIter = 2 * d;          // K-chunks of 32

    const int Abase = 16384 * off;
    const int Bbase = 4096 * off;

    // epilogue column offsets
    if (tid < 64) {
        const int gc = tileN * 64 + tid;
        const int o  = gc / d;
        const int v  = gc - o * d;
        colOff[tid] = o * IRREP + v * d;
    }

    // ---- per-thread cp.async geometry ----
    const int arow = tid & 127;
    const int acsel = (tid >> 7) * 2;           // chunks acsel, acsel+1
    const int asw = (arow >> 1) & 3;
    const uint32_t adst0 = (uint32_t)(arow * 64 + (((acsel + 0) ^ asw) << 4));
    const uint32_t adst1 = (uint32_t)(arow * 64 + (((acsel + 1) ^ asw) << 4));
    const int asrcRow = Abase + (tileM * 128 + arow) * Kl;   // + kt + chunk*8

    const int brow = tid >> 2;
    const int bcsel = tid & 3;
    const uint32_t bdst = (uint32_t)(brow * 64 + ((bcsel ^ ((brow >> 1) & 3)) << 4));
    const int bsrcRow = Bbase + (tileN * 64 + brow) * Kl;

    // ---- per-lane ldmatrix geometry ----
    // A: lanes 0-15 rows, lanes 16-31 rows w/ +8 k-chunk
    const int a_r0 = wm * 32 + (lane & 15);           // + mt*16
    const int a_cbit = lane >> 4;
    // B: x4 covering n16 x k16
    const int b_r0 = wn * 32 + (lane & 7) + ((lane >> 4) << 3);  // + ntg*16
    const int b_cbit = (lane >> 3) & 1;

    uint32_t aoff[2][2], boff[2][2];   // [mt or ntg][ks]
#pragma unroll
    for (int mt = 0; mt < 2; mt++) {
        const int row = a_r0 + mt * 16;
        const int sw = (row >> 1) & 3;
#pragma unroll
        for (int ks = 0; ks < 2; ks++)
            aoff[mt][ks] = (uint32_t)(row * 64 + (((ks * 2 + a_cbit) ^ sw) << 4));
    }
#pragma unroll
    for (int ng = 0; ng < 2; ng++) {
        const int row = b_r0 + ng * 16;
        const int sw = (row >> 1) & 3;
#pragma unroll
        for (int ks = 0; ks < 2; ks++)
            boff[ng][ks] = (uint32_t)(row * 64 + (((ks * 2 + b_cbit) ^ sw) << 4));
    }

    // ---- prologue: stages 0..2 ----
#pragma unroll
    for (int s = 0; s < 3; s++) {
        if (s < nIter) {
            const uint32_t dst = sb + (uint32_t)(s & 3) * STAGE_BYTES;
            const int kt = s * 32;
            cp16(dst + OFF_SA_HI + adst0, g_Ahi + asrcRow + kt + (acsel + 0) * 8);
            cp16(dst + OFF_SA_HI + adst1, g_Ahi + asrcRow + kt + (acsel + 1) * 8);
            cp16(dst + OFF_SA_LO + adst0, g_Alo + asrcRow + kt + (acsel + 0) * 8);
            cp16(dst + OFF_SA_LO + adst1, g_Alo + asrcRow + kt + (acsel + 1) * 8);
            cp16(dst + OFF_SB_HI + bdst,  g_Bhi + bsrcRow + kt + bcsel * 8);
            cp16(dst + OFF_SB_LO + bdst,  g_Blo + bsrcRow + kt + bcsel * 8);
        }
        CP_COMMIT();
    }

    float acc[2][4][4] = {};

    for (int it = 0; it < nIter; ++it) {
        CP_WAIT2();
        __syncthreads();

        // issue stage it+3 into slot (it+3)&3 (read as stage it-1 last iter)
        {
            const int s = it + 3;
            if (s < nIter) {
                const uint32_t dst = sb + (uint32_t)(s & 3) * STAGE_BYTES;
                const int kt = s * 32;
                cp16(dst + OFF_SA_HI + adst0, g_Ahi + asrcRow + kt + (acsel + 0) * 8);
                cp16(dst + OFF_SA_HI + adst1, g_Ahi + asrcRow + kt + (acsel + 1) * 8);
                cp16(dst + OFF_SA_LO + adst0, g_Alo + asrcRow + kt + (acsel + 0) * 8);
                cp16(dst + OFF_SA_LO + adst1, g_Alo + asrcRow + kt + (acsel + 1) * 8);
                cp16(dst + OFF_SB_HI + bdst,  g_Bhi + bsrcRow + kt + bcsel * 8);
                cp16(dst + OFF_SB_LO + bdst,  g_Blo + bsrcRow + kt + bcsel * 8);
            }
            CP_COMMIT();
        }

        const uint32_t sbase = sb + (uint32_t)(it & 3) * STAGE_BYTES;
#pragma unroll
        for (int ks = 0; ks < 2; ks++) {
            uint32_t ah[2][4], al[2][4], bh[2][4], bl[2][4];
#pragma unroll
            for (int mt = 0; mt < 2; mt++) {
                LDSM_X4(ah[mt][0], ah[mt][1], ah[mt][2], ah[mt][3],
                        sbase + OFF_SA_HI + aoff[mt][ks]);
                LDSM_X4(al[mt][0], al[mt][1], al[mt][2], al[mt][3],
                        sbase + OFF_SA_LO + aoff[mt][ks]);
            }
#pragma unroll
            for (int ng = 0; ng < 2; ng++) {
                LDSM_X4(bh[ng][0], bh[ng][1], bh[ng][2], bh[ng][3],
                        sbase + OFF_SB_HI + boff[ng][ks]);
                LDSM_X4(bl[ng][0], bl[ng][1], bl[ng][2], bl[ng][3],
                        sbase + OFF_SB_LO + boff[ng][ks]);
            }
#pragma unroll
            for (int mt = 0; mt < 2; mt++)
#pragma unroll
                for (int nt = 0; nt < 4; nt++) {
                    const int ng = nt >> 1, pr = (nt & 1) * 2;
                    mma_bf16(acc[mt][nt], ah[mt], bh[ng][pr], bh[ng][pr + 1]);
                    mma_bf16(acc[mt][nt], ah[mt], bl[ng][pr], bl[ng][pr + 1]);
                    mma_bf16(acc[mt][nt], al[mt], bh[ng][pr], bh[ng][pr + 1]);
                }
        }
    }

    // ---- epilogue: scatter f32 with alpha ----
    const float alpha = rsqrtf(64.0f * (float)d);
#pragma unroll
    for (int mt = 0; mt < 2; mt++)
#pragma unroll
        for (int h = 0; h < 2; h++) {
            const int r = tileM * 128 + wm * 32 + mt * 16 + (lane >> 2) + h * 8;
            const int b = r / d;
            const int m = r - b * d;
            float* orow = O + b * RSTRIDE + off + m;
#pragma unroll
            for (int nt = 0; nt < 4; nt++) {
                const int c0 = wn * 32 + nt * 8 + (lane & 3) * 2;
                orow[colOff[c0]]     = acc[mt][nt][h * 2 + 0] * alpha;
                orow[colOff[c0 + 1]] = acc[mt][nt][h * 2 + 1] * alpha;
            }
        }
}

// ---------------------------------------------------------------------------
// Launch: inputs: x (256,64,1771) f32, D (512,1771) f32, w (64,64,512) f32.
// ---------------------------------------------------------------------------
extern "C" void kernel_launch(void* const* d_in, const int* in_sizes, int n_in,
                              void* d_out, int out_size) {
    const float* x = (const float*)d_in[0];
    const float* D = (const float*)d_in[1];
    const float* w = (const float*)d_in[2];
    float* out = (float*)d_out;

    cudaFuncSetAttribute(xprep_kernel, cudaFuncAttributeMaxDynamicSharedMemorySize, 112896);
    cudaFuncSetAttribute(so3_kernel,  cudaFuncAttributeMaxDynamicSharedMemorySize, SO3_SMEM);

    xprep_kernel<<<dim3(BATCH, 11), 256, 112896>>>(x);   // x -> A planes
    psi_kernel<<<dim3(28, 64), 256>>>(w, D);             // W@D -> B planes
    so3_kernel<<<3542, 256, SO3_SMEM>>>(out);
}

// round 6
// speedup vs baseline: 2.0979x; 1.2496x over previous
#include <cuda_runtime.h>
#include <cuda_bf16.h>
#include <cstdint>

// Problem constants
#define F_IN   64
#define F_OUT  64
#define IRREP  1771
#define NGRID  512
#define BATCH  256
#define RSTRIDE (F_OUT * IRREP)   // 113344

// bf16 hi/lo planes.
// A_l: rows r=(b*d+m) [256d], cols k=(i*d+u) [64d]; base elem = 16384*c_off[l]
// B_l: rows n=(o*d+v) [64d],  cols k=(i*d+u) [64d]; base elem =  4096*c_off[l]
#define AELEMS 29016064   // 16384*1771
#define BELEMS 7254016    // 4096*1771
__device__ __nv_bfloat16 g_Ahi[AELEMS];
__device__ __nv_bfloat16 g_Alo[AELEMS];
__device__ __nv_bfloat16 g_Bhi[BELEMS];
__device__ __nv_bfloat16 g_Blo[BELEMS];

// stage-2 blocks per l = 2*d*d (tile 128x64); cumulative
__constant__ int c_cum2[12] = {0, 2, 20, 70, 168, 330, 572, 910, 1360, 1938, 2660, 3542};
// cumsum of d^2 (12 entries so [l+1] is always valid)
__constant__ int c_off12[12] = {0, 1, 10, 35, 84, 165, 286, 455, 680, 969, 1330, 1771};

// ---------------------------------------------------------------------------
// helpers
// ---------------------------------------------------------------------------
__device__ __forceinline__ uint32_t smem_u32(const void* p) {
    uint32_t a;
    asm("{ .reg .u64 t; cvta.to.shared.u64 t, %1; cvt.u32.u64 %0, t; }" : "=r"(a) : "l"(p));
    return a;
}

__device__ __forceinline__ void cp16(uint32_t dst, const void* src) {
    asm volatile("cp.async.cg.shared.global [%0], [%1], 16;"
                 :: "r"(dst), "l"((uint64_t)__cvta_generic_to_global(src)) : "memory");
}
#define CP_COMMIT() asm volatile("cp.async.commit_group;" ::: "memory")
#define CP_WAIT2()  asm volatile("cp.async.wait_group 2;" ::: "memory")

#define LDSM_X4(r0, r1, r2, r3, addr) \
    asm volatile("ldmatrix.sync.aligned.m8n8.x4.shared.b16 {%0,%1,%2,%3}, [%4];" \
                 : "=r"(r0), "=r"(r1), "=r"(r2), "=r"(r3) : "r"(addr))

__device__ __forceinline__ void mma_bf16(float* c, const uint32_t* a, uint32_t b0, uint32_t b1) {
    asm volatile(
        "mma.sync.aligned.m16n8k16.row.col.f32.bf16.bf16.f32 "
        "{%0,%1,%2,%3}, {%4,%5,%6,%7}, {%8,%9}, {%0,%1,%2,%3};"
        : "+f"(c[0]), "+f"(c[1]), "+f"(c[2]), "+f"(c[3])
        : "r"(a[0]), "r"(a[1]), "r"(a[2]), "r"(a[3]), "r"(b0), "r"(b1));
}

__device__ __forceinline__ uint32_t packbf2(float a, float b) {
    uint16_t x = __bfloat16_as_ushort(__float2bfloat16(a));
    uint16_t y = __bfloat16_as_ushort(__float2bfloat16(b));
    return (uint32_t)x | ((uint32_t)y << 16);
}

// ---------------------------------------------------------------------------
// Kernel 0: xprep v2 — x (B, F_IN, IRREP) f32 -> per-l bf16 hi/lo A planes.
// Grid (b, l, ichunk): CTA handles 16 input channels i = ic*16 .. ic*16+15.
// Static smem 16 x d2 floats (<= 28224 B). Divmods hoisted: 2 per thread total.
// Thread t handles k-pair (2t, 2t+1) within the 16d-column chunk, loops over m.
// ---------------------------------------------------------------------------
__global__ __launch_bounds__(256) void xprep_kernel(const float* __restrict__ X) {
    __shared__ float sm[16 * 441];
    const int b  = blockIdx.x;
    const int l  = blockIdx.y;
    const int ic = blockIdx.z;          // 0..3 (16 i's each)
    const int d  = 2 * l + 1;
    const int d2 = d * d;
    const int off = c_off12[l];
    const int Kl = 64 * d;
    const int tid = threadIdx.x;

    // Phase 1: coalesced load of x[b][ic*16 .. +15][off .. off+d2)
    const float* xb = X + (size_t)b * RSTRIDE + (ic * 16) * IRREP + off;
#pragma unroll 4
    for (int ii = 0; ii < 16; ii++)
        for (int j = tid; j < d2; j += 256)
            sm[ii * d2 + j] = xb[ii * IRREP + j];
    __syncthreads();

    // Phase 2: thread t covers k-pair (2t, 2t+1); valid t < 8d
    if (tid < 8 * d) {
        const int k0 = 2 * tid;
        const int k1 = k0 + 1;
        const int i0 = k0 / d, u0 = k0 - i0 * d;      // hoisted divmods
        const int i1 = k1 / d, u1 = k1 - i1 * d;
        const int s0 = i0 * d2 + u0 * d;
        const int s1 = i1 * d2 + u1 * d;

        const int Abase = 16384 * off;
        const int colBase = ic * 16 * d + k0;          // even -> 4B aligned
        int rowIdx = (b * d) * Kl + colBase;
        for (int m = 0; m < d; m++, rowIdx += Kl) {
            const float v0 = sm[s0 + m];
            const float v1 = sm[s1 + m];
            const float h0 = __bfloat162float(__float2bfloat16(v0));
            const float h1 = __bfloat162float(__float2bfloat16(v1));
            *(uint32_t*)(g_Ahi + Abase + rowIdx) = packbf2(v0, v1);
            *(uint32_t*)(g_Alo + Abase + rowIdx) = packbf2(v0 - h0, v1 - h1);
        }
    }
}

// ---------------------------------------------------------------------------
// Kernel 1: psi GEMM (fp32 SIMT) -> scatter into bf16 hi/lo B planes.
// psi[r=(i*64+o)][c] = (1/sqrt(512)) * sum_n W[r][n] * D[n][c]
// B_l[(o*d+v)][(i*d+u)] with c = off + u*d + v.  alpha = 1/sqrt(64 d) folded in.
// ---------------------------------------------------------------------------
__global__ __launch_bounds__(256) void psi_kernel(const float* __restrict__ W,
                                                  const float* __restrict__ D) {
    __shared__ float As[16 * 68];
    __shared__ float Bs[16 * 68];

    const int tid   = threadIdx.x;
    const int tileN = blockIdx.x;   // 0..27
    const int tileM = blockIdx.y;   // 0..63

    const int lk16 = tid & 15;
    const int lr16 = tid >> 4;
    const int lcol = tid & 63;
    const int lk4  = tid >> 6;
    const int gcolb = tileN * 64 + lcol;

    const float* wbase = W + (tileM * 64 + lr16) * NGRID + lk16;
    const int tx = tid & 15;
    const int ty = tid >> 4;
    float acc[4][4] = {};

    for (int kt = 0; kt < NGRID; kt += 16) {
#pragma unroll
        for (int j = 0; j < 4; j++)
            As[lk16 * 68 + lr16 + 16 * j] = wbase[(16 * j) * NGRID + kt];
#pragma unroll
        for (int j = 0; j < 4; j++) {
            const int krow = lk4 + 4 * j;
            Bs[krow * 68 + lcol] = (gcolb < IRREP) ? D[(kt + krow) * IRREP + gcolb] : 0.0f;
        }
        __syncthreads();
#pragma unroll
        for (int kk = 0; kk < 16; kk++) {
            const float4 av = *(const float4*)&As[kk * 68 + ty * 4];
            const float4 bv = *(const float4*)&Bs[kk * 68 + tx * 4];
            const float aarr[4] = {av.x, av.y, av.z, av.w};
            const float barr[4] = {bv.x, bv.y, bv.z, bv.w};
#pragma unroll
            for (int ii = 0; ii < 4; ii++)
#pragma unroll
                for (int jj = 0; jj < 4; jj++)
                    acc[ii][jj] = fmaf(aarr[ii], barr[jj], acc[ii][jj]);
        }
        __syncthreads();
    }

    const float scale = 0.04419417382415922f;  // 1/sqrt(512)
#pragma unroll
    for (int cc = 0; cc < 4; cc++) {
        const int gcol = tileN * 64 + tx * 4 + cc;
        if (gcol >= IRREP) continue;
        int l = 0;
        while (gcol >= c_off12[l + 1]) ++l;
        const int d   = 2 * l + 1;
        const int off = c_off12[l];
        const int rel = gcol - off;
        const int u = rel / d;
        const int v = rel - u * d;
        const int Bbase = 4096 * off;
        const int Kl = 64 * d;
        const float sa = scale * rsqrtf(64.0f * (float)d);  // fold alpha into B
#pragma unroll
        for (int rr = 0; rr < 4; rr++) {
            const int grow = tileM * 64 + ty * 4 + rr;
            const int i = grow >> 6;
            const int o = grow & 63;
            const float val = acc[rr][cc] * sa;
            const __nv_bfloat16 h = __float2bfloat16(val);
            const __nv_bfloat16 lw = __float2bfloat16(val - __bfloat162float(h));
            const int idx = Bbase + (o * d + v) * Kl + (i * d + u);
            g_Bhi[idx] = h;
            g_Blo[idx] = lw;
        }
    }
}

// ---------------------------------------------------------------------------
// Kernel 2: so3 GEMM per l via mma.sync bf16 (3-product split).
// CTA tile 128x64, K-chunk 32, 8 warps (4x2 of 32x32), 4-stage cp.async.
// ---------------------------------------------------------------------------
#define STAGE_BYTES 24576
#define OFF_SA_HI 0
#define OFF_SA_LO 8192
#define OFF_SB_HI 16384
#define OFF_SB_LO 20480
#define SO3_SMEM (4 * STAGE_BYTES)

__global__ __launch_bounds__(256, 2) void so3_kernel(float* __restrict__ O) {
    extern __shared__ __align__(1024) char dsm[];
    __shared__ int colOff[64];
    const uint32_t sb = smem_u32(dsm);

    const int tid  = threadIdx.x;
    const int wid  = tid >> 5;
    const int lane = tid & 31;
    const int wm = wid >> 1;     // 0..3  (m tile of 32)
    const int wn = wid & 1;      // 0..1  (n tile of 32)

    // tile mapping (reversed: largest l first)
    const int bid = (int)gridDim.x - 1 - (int)blockIdx.x;
    int l = 0;
    while (bid >= c_cum2[l + 1]) ++l;
    const int d     = 2 * l + 1;
    const int off   = c_off12[l];
    const int loc   = bid - c_cum2[l];
    const int tileM = loc / d;
    const int tileN = loc - tileM * d;
    const int Kl    = 64 * d;
    const int nIter = 2 * d;          // K-chunks of 32

    const int Abase = 16384 * off;
    const int Bbase = 4096 * off;

    // epilogue column offsets
    if (tid < 64) {
        const int gc = tileN * 64 + tid;
        const int o  = gc / d;
        const int v  = gc - o * d;
        colOff[tid] = o * IRREP + v * d;
    }

    // ---- per-thread cp.async geometry ----
    const int arow = tid & 127;
    const int acsel = (tid >> 7) * 2;           // chunks acsel, acsel+1
    const int asw = (arow >> 1) & 3;
    const uint32_t adst0 = (uint32_t)(arow * 64 + (((acsel + 0) ^ asw) << 4));
    const uint32_t adst1 = (uint32_t)(arow * 64 + (((acsel + 1) ^ asw) << 4));
    const int asrcRow = Abase + (tileM * 128 + arow) * Kl;   // + kt + chunk*8

    const int brow = tid >> 2;
    const int bcsel = tid & 3;
    const uint32_t bdst = (uint32_t)(brow * 64 + ((bcsel ^ ((brow >> 1) & 3)) << 4));
    const int bsrcRow = Bbase + (tileN * 64 + brow) * Kl;

    // ---- per-lane ldmatrix geometry ----
    const int a_r0 = wm * 32 + (lane & 15);
    const int a_cbit = lane >> 4;
    const int b_r0 = wn * 32 + (lane & 7) + ((lane >> 4) << 3);
    const int b_cbit = (lane >> 3) & 1;

    uint32_t aoff[2][2], boff[2][2];
#pragma unroll
    for (int mt = 0; mt < 2; mt++) {
        const int row = a_r0 + mt * 16;
        const int sw = (row >> 1) & 3;
#pragma unroll
        for (int ks = 0; ks < 2; ks++)
            aoff[mt][ks] = (uint32_t)(row * 64 + (((ks * 2 + a_cbit) ^ sw) << 4));
    }
#pragma unroll
    for (int ng = 0; ng < 2; ng++) {
        const int row = b_r0 + ng * 16;
        const int sw = (row >> 1) & 3;
#pragma unroll
        for (int ks = 0; ks < 2; ks++)
            boff[ng][ks] = (uint32_t)(row * 64 + (((ks * 2 + b_cbit) ^ sw) << 4));
    }

    // ---- prologue: stages 0..2 ----
#pragma unroll
    for (int s = 0; s < 3; s++) {
        if (s < nIter) {
            const uint32_t dst = sb + (uint32_t)(s & 3) * STAGE_BYTES;
            const int kt = s * 32;
            cp16(dst + OFF_SA_HI + adst0, g_Ahi + asrcRow + kt + (acsel + 0) * 8);
            cp16(dst + OFF_SA_HI + adst1, g_Ahi + asrcRow + kt + (acsel + 1) * 8);
            cp16(dst + OFF_SA_LO + adst0, g_Alo + asrcRow + kt + (acsel + 0) * 8);
            cp16(dst + OFF_SA_LO + adst1, g_Alo + asrcRow + kt + (acsel + 1) * 8);
            cp16(dst + OFF_SB_HI + bdst,  g_Bhi + bsrcRow + kt + bcsel * 8);
            cp16(dst + OFF_SB_LO + bdst,  g_Blo + bsrcRow + kt + bcsel * 8);
        }
        CP_COMMIT();
    }

    float acc[2][4][4] = {};

    for (int it = 0; it < nIter; ++it) {
        CP_WAIT2();
        __syncthreads();

        {
            const int s = it + 3;
            if (s < nIter) {
                const uint32_t dst = sb + (uint32_t)(s & 3) * STAGE_BYTES;
                const int kt = s * 32;
                cp16(dst + OFF_SA_HI + adst0, g_Ahi + asrcRow + kt + (acsel + 0) * 8);
                cp16(dst + OFF_SA_HI + adst1, g_Ahi + asrcRow + kt + (acsel + 1) * 8);
                cp16(dst + OFF_SA_LO + adst0, g_Alo + asrcRow + kt + (acsel + 0) * 8);
                cp16(dst + OFF_SA_LO + adst1, g_Alo + asrcRow + kt + (acsel + 1) * 8);
                cp16(dst + OFF_SB_HI + bdst,  g_Bhi + bsrcRow + kt + bcsel * 8);
                cp16(dst + OFF_SB_LO + bdst,  g_Blo + bsrcRow + kt + bcsel * 8);
            }
            CP_COMMIT();
        }

        const uint32_t sbase = sb + (uint32_t)(it & 3) * STAGE_BYTES;
#pragma unroll
        for (int ks = 0; ks < 2; ks++) {
            uint32_t ah[2][4], al[2][4], bh[2][4], bl[2][4];
#pragma unroll
            for (int mt = 0; mt < 2; mt++) {
                LDSM_X4(ah[mt][0], ah[mt][1], ah[mt][2], ah[mt][3],
                        sbase + OFF_SA_HI + aoff[mt][ks]);
                LDSM_X4(al[mt][0], al[mt][1], al[mt][2], al[mt][3],
                        sbase + OFF_SA_LO + aoff[mt][ks]);
            }
#pragma unroll
            for (int ng = 0; ng < 2; ng++) {
                LDSM_X4(bh[ng][0], bh[ng][1], bh[ng][2], bh[ng][3],
                        sbase + OFF_SB_HI + boff[ng][ks]);
                LDSM_X4(bl[ng][0], bl[ng][1], bl[ng][2], bl[ng][3],
                        sbase + OFF_SB_LO + boff[ng][ks]);
            }
#pragma unroll
            for (int mt = 0; mt < 2; mt++)
#pragma unroll
                for (int nt = 0; nt < 4; nt++) {
                    const int ng = nt >> 1, pr = (nt & 1) * 2;
                    mma_bf16(acc[mt][nt], ah[mt], bh[ng][pr], bh[ng][pr + 1]);
                    mma_bf16(acc[mt][nt], ah[mt], bl[ng][pr], bl[ng][pr + 1]);
                    mma_bf16(acc[mt][nt], al[mt], bh[ng][pr], bh[ng][pr + 1]);
                }
        }
    }

    // ---- epilogue: scatter f32 (alpha already folded into B planes) ----
#pragma unroll
    for (int mt = 0; mt < 2; mt++)
#pragma unroll
        for (int h = 0; h < 2; h++) {
            const int r = tileM * 128 + wm * 32 + mt * 16 + (lane >> 2) + h * 8;
            const int b = r / d;
            const int m = r - b * d;
            float* orow = O + b * RSTRIDE + off + m;
#pragma unroll
            for (int nt = 0; nt < 4; nt++) {
                const int c0 = wn * 32 + nt * 8 + (lane & 3) * 2;
                orow[colOff[c0]]     = acc[mt][nt][h * 2 + 0];
                orow[colOff[c0 + 1]] = acc[mt][nt][h * 2 + 1];
            }
        }
}

// ---------------------------------------------------------------------------
// Launch: inputs: x (256,64,1771) f32, D (512,1771) f32, w (64,64,512) f32.
// ---------------------------------------------------------------------------
extern "C" void kernel_launch(void* const* d_in, const int* in_sizes, int n_in,
                              void* d_out, int out_size) {
    const float* x = (const float*)d_in[0];
    const float* D = (const float*)d_in[1];
    const float* w = (const float*)d_in[2];
    float* out = (float*)d_out;

    cudaFuncSetAttribute(so3_kernel, cudaFuncAttributeMaxDynamicSharedMemorySize, SO3_SMEM);

    xprep_kernel<<<dim3(BATCH, 11, 4), 256>>>(x);        // x -> A planes
    psi_kernel<<<dim3(28, 64), 256>>>(w, D);             // W@D -> B planes (alpha folded)
    so3_kernel<<<3542, 256, SO3_SMEM>>>(out);
}

// round 7
// speedup vs baseline: 3.5575x; 1.6958x over previous
#include <cuda_runtime.h>
#include <cuda_fp16.h>
#include <cstdint>

// Problem constants
#define F_IN   64
#define F_OUT  64
#define IRREP  1771
#define NGRID  512
#define BATCH  256
#define RSTRIDE (F_OUT * IRREP)   // 113344

// fp16 planes.
// A_l: rows r=(b*d+m) [256d], cols k=(i*d+u) [64d]; base elem = 16384*c_off[l]
// B_l: rows n=(o*d+v) [64d],  cols k=(i*d+u) [64d]; base elem =  4096*c_off[l]
//      (alpha = 1/sqrt(64 d) folded into B)
#define AELEMS 29016064   // 16384*1771
#define BELEMS 7254016    // 4096*1771
__device__ __half g_Ah[AELEMS];
__device__ __half g_Bh[BELEMS];

// stage-2 blocks per l = 2*d*d (tile 128x64); cumulative
__constant__ int c_cum2[12] = {0, 2, 20, 70, 168, 330, 572, 910, 1360, 1938, 2660, 3542};
// cumsum of d^2 (12 entries so [l+1] is always valid)
__constant__ int c_off12[12] = {0, 1, 10, 35, 84, 165, 286, 455, 680, 969, 1330, 1771};

// ---------------------------------------------------------------------------
// helpers
// ---------------------------------------------------------------------------
__device__ __forceinline__ uint32_t smem_u32(const void* p) {
    uint32_t a;
    asm("{ .reg .u64 t; cvta.to.shared.u64 t, %1; cvt.u32.u64 %0, t; }" : "=r"(a) : "l"(p));
    return a;
}

__device__ __forceinline__ void cp16(uint32_t dst, const void* src) {
    asm volatile("cp.async.cg.shared.global [%0], [%1], 16;"
                 :: "r"(dst), "l"((uint64_t)__cvta_generic_to_global(src)) : "memory");
}
#define CP_COMMIT() asm volatile("cp.async.commit_group;" ::: "memory")
#define CP_WAIT2()  asm volatile("cp.async.wait_group 2;" ::: "memory")

#define LDSM_X4(r0, r1, r2, r3, addr) \
    asm volatile("ldmatrix.sync.aligned.m8n8.x4.shared.b16 {%0,%1,%2,%3}, [%4];" \
                 : "=r"(r0), "=r"(r1), "=r"(r2), "=r"(r3) : "r"(addr))

__device__ __forceinline__ void mma_f16(float* c, const uint32_t* a, uint32_t b0, uint32_t b1) {
    asm volatile(
        "mma.sync.aligned.m16n8k16.row.col.f32.f16.f16.f32 "
        "{%0,%1,%2,%3}, {%4,%5,%6,%7}, {%8,%9}, {%0,%1,%2,%3};"
        : "+f"(c[0]), "+f"(c[1]), "+f"(c[2]), "+f"(c[3])
        : "r"(a[0]), "r"(a[1]), "r"(a[2]), "r"(a[3]), "r"(b0), "r"(b1));
}

__device__ __forceinline__ uint32_t packh2(float a, float b) {
    __half2 h = __floats2half2_rn(a, b);
    return *(uint32_t*)&h;
}

// ---------------------------------------------------------------------------
// Kernel 0: xprep — x (B, F_IN, IRREP) f32 -> per-l fp16 A planes.
// Grid (b, l, ichunk): CTA handles 16 input channels. Divmods hoisted.
// ---------------------------------------------------------------------------
__global__ __launch_bounds__(256) void xprep_kernel(const float* __restrict__ X) {
    __shared__ float sm[16 * 441];
    const int b  = blockIdx.x;
    const int l  = blockIdx.y;
    const int ic = blockIdx.z;          // 0..3 (16 i's each)
    const int d  = 2 * l + 1;
    const int d2 = d * d;
    const int off = c_off12[l];
    const int Kl = 64 * d;
    const int tid = threadIdx.x;

    const float* xb = X + (size_t)b * RSTRIDE + (ic * 16) * IRREP + off;
#pragma unroll 4
    for (int ii = 0; ii < 16; ii++)
        for (int j = tid; j < d2; j += 256)
            sm[ii * d2 + j] = xb[ii * IRREP + j];
    __syncthreads();

    if (tid < 8 * d) {
        const int k0 = 2 * tid;
        const int k1 = k0 + 1;
        const int i0 = k0 / d, u0 = k0 - i0 * d;      // hoisted divmods
        const int i1 = k1 / d, u1 = k1 - i1 * d;
        const int s0 = i0 * d2 + u0 * d;
        const int s1 = i1 * d2 + u1 * d;

        const int Abase = 16384 * off;
        const int colBase = ic * 16 * d + k0;          // even -> 4B aligned
        int rowIdx = (b * d) * Kl + colBase;
        for (int m = 0; m < d; m++, rowIdx += Kl) {
            *(uint32_t*)(g_Ah + Abase + rowIdx) = packh2(sm[s0 + m], sm[s1 + m]);
        }
    }
}

// ---------------------------------------------------------------------------
// Kernel 1: psi GEMM (fp32 SIMT) -> scatter into fp16 B planes (alpha folded).
// psi[r=(i*64+o)][c] = (1/sqrt(512)) * sum_n W[r][n] * D[n][c]
// B_l[(o*d+v)][(i*d+u)] with c = off + u*d + v.
// ---------------------------------------------------------------------------
__global__ __launch_bounds__(256) void psi_kernel(const float* __restrict__ W,
                                                  const float* __restrict__ D) {
    __shared__ float As[16 * 68];
    __shared__ float Bs[16 * 68];

    const int tid   = threadIdx.x;
    const int tileN = blockIdx.x;   // 0..27
    const int tileM = blockIdx.y;   // 0..63

    const int lk16 = tid & 15;
    const int lr16 = tid >> 4;
    const int lcol = tid & 63;
    const int lk4  = tid >> 6;
    const int gcolb = tileN * 64 + lcol;

    const float* wbase = W + (tileM * 64 + lr16) * NGRID + lk16;
    const int tx = tid & 15;
    const int ty = tid >> 4;
    float acc[4][4] = {};

    for (int kt = 0; kt < NGRID; kt += 16) {
#pragma unroll
        for (int j = 0; j < 4; j++)
            As[lk16 * 68 + lr16 + 16 * j] = wbase[(16 * j) * NGRID + kt];
#pragma unroll
        for (int j = 0; j < 4; j++) {
            const int krow = lk4 + 4 * j;
            Bs[krow * 68 + lcol] = (gcolb < IRREP) ? D[(kt + krow) * IRREP + gcolb] : 0.0f;
        }
        __syncthreads();
#pragma unroll
        for (int kk = 0; kk < 16; kk++) {
            const float4 av = *(const float4*)&As[kk * 68 + ty * 4];
            const float4 bv = *(const float4*)&Bs[kk * 68 + tx * 4];
            const float aarr[4] = {av.x, av.y, av.z, av.w};
            const float barr[4] = {bv.x, bv.y, bv.z, bv.w};
#pragma unroll
            for (int ii = 0; ii < 4; ii++)
#pragma unroll
                for (int jj = 0; jj < 4; jj++)
                    acc[ii][jj] = fmaf(aarr[ii], barr[jj], acc[ii][jj]);
        }
        __syncthreads();
    }

    const float scale = 0.04419417382415922f;  // 1/sqrt(512)
#pragma unroll
    for (int cc = 0; cc < 4; cc++) {
        const int gcol = tileN * 64 + tx * 4 + cc;
        if (gcol >= IRREP) continue;
        int l = 0;
        while (gcol >= c_off12[l + 1]) ++l;
        const int d   = 2 * l + 1;
        const int off = c_off12[l];
        const int rel = gcol - off;
        const int u = rel / d;
        const int v = rel - u * d;
        const int Bbase = 4096 * off;
        const int Kl = 64 * d;
        const float sa = scale * rsqrtf(64.0f * (float)d);  // fold alpha into B
#pragma unroll
        for (int rr = 0; rr < 4; rr++) {
            const int grow = tileM * 64 + ty * 4 + rr;
            const int i = grow >> 6;
            const int o = grow & 63;
            g_Bh[Bbase + (o * d + v) * Kl + (i * d + u)] = __float2half_rn(acc[rr][cc] * sa);
        }
    }
}

// ---------------------------------------------------------------------------
// Kernel 2: so3 GEMM per l via mma.sync fp16 (single product).
// CTA tile 128x64, K-chunk 32, 8 warps (4x2 of 32x32), 4-stage cp.async.
// smem per stage: A 8K | B 4K = 12KB.
// Swizzle: byte = row*64 + ((chunk ^ ((row>>1)&3))<<4), chunk = k/8.
// ---------------------------------------------------------------------------
#define STAGE_BYTES 12288
#define OFF_SA 0
#define OFF_SB 8192
#define SO3_SMEM (4 * STAGE_BYTES)

__global__ __launch_bounds__(256, 3) void so3_kernel(float* __restrict__ O) {
    extern __shared__ __align__(1024) char dsm[];
    __shared__ int colOff[64];
    const uint32_t sb = smem_u32(dsm);

    const int tid  = threadIdx.x;
    const int wid  = tid >> 5;
    const int lane = tid & 31;
    const int wm = wid >> 1;     // 0..3  (m tile of 32)
    const int wn = wid & 1;      // 0..1  (n tile of 32)

    // tile mapping (reversed: largest l first)
    const int bid = (int)gridDim.x - 1 - (int)blockIdx.x;
    int l = 0;
    while (bid >= c_cum2[l + 1]) ++l;
    const int d     = 2 * l + 1;
    const int off   = c_off12[l];
    const int loc   = bid - c_cum2[l];
    const int tileM = loc / d;
    const int tileN = loc - tileM * d;
    const int Kl    = 64 * d;
    const int nIter = 2 * d;          // K-chunks of 32

    const int Abase = 16384 * off;
    const int Bbase = 4096 * off;

    // epilogue column offsets
    if (tid < 64) {
        const int gc = tileN * 64 + tid;
        const int o  = gc / d;
        const int v  = gc - o * d;
        colOff[tid] = o * IRREP + v * d;
    }

    // ---- per-thread cp.async geometry ----
    const int arow = tid & 127;
    const int acsel = (tid >> 7) * 2;           // chunks acsel, acsel+1
    const int asw = (arow >> 1) & 3;
    const uint32_t adst0 = (uint32_t)(arow * 64 + (((acsel + 0) ^ asw) << 4));
    const uint32_t adst1 = (uint32_t)(arow * 64 + (((acsel + 1) ^ asw) << 4));
    const int asrcRow = Abase + (tileM * 128 + arow) * Kl;   // + kt + chunk*8

    const int brow = tid >> 2;
    const int bcsel = tid & 3;
    const uint32_t bdst = (uint32_t)(brow * 64 + ((bcsel ^ ((brow >> 1) & 3)) << 4));
    const int bsrcRow = Bbase + (tileN * 64 + brow) * Kl;

    // ---- per-lane ldmatrix geometry ----
    const int a_r0 = wm * 32 + (lane & 15);
    const int a_cbit = lane >> 4;
    const int b_r0 = wn * 32 + (lane & 7) + ((lane >> 4) << 3);
    const int b_cbit = (lane >> 3) & 1;

    uint32_t aoff[2][2], boff[2][2];
#pragma unroll
    for (int mt = 0; mt < 2; mt++) {
        const int row = a_r0 + mt * 16;
        const int sw = (row >> 1) & 3;
#pragma unroll
        for (int ks = 0; ks < 2; ks++)
            aoff[mt][ks] = (uint32_t)(row * 64 + (((ks * 2 + a_cbit) ^ sw) << 4));
    }
#pragma unroll
    for (int ng = 0; ng < 2; ng++) {
        const int row = b_r0 + ng * 16;
        const int sw = (row >> 1) & 3;
#pragma unroll
        for (int ks = 0; ks < 2; ks++)
            boff[ng][ks] = (uint32_t)(row * 64 + (((ks * 2 + b_cbit) ^ sw) << 4));
    }

    // ---- prologue: stages 0..2 ----
#pragma unroll
    for (int s = 0; s < 3; s++) {
        if (s < nIter) {
            const uint32_t dst = sb + (uint32_t)(s & 3) * STAGE_BYTES;
            const int kt = s * 32;
            cp16(dst + OFF_SA + adst0, g_Ah + asrcRow + kt + (acsel + 0) * 8);
            cp16(dst + OFF_SA + adst1, g_Ah + asrcRow + kt + (acsel + 1) * 8);
            cp16(dst + OFF_SB + bdst,  g_Bh + bsrcRow + kt + bcsel * 8);
        }
        CP_COMMIT();
    }

    float acc[2][4][4] = {};

    for (int it = 0; it < nIter; ++it) {
        CP_WAIT2();
        __syncthreads();

        {
            const int s = it + 3;
            if (s < nIter) {
                const uint32_t dst = sb + (uint32_t)(s & 3) * STAGE_BYTES;
                const int kt = s * 32;
                cp16(dst + OFF_SA + adst0, g_Ah + asrcRow + kt + (acsel + 0) * 8);
                cp16(dst + OFF_SA + adst1, g_Ah + asrcRow + kt + (acsel + 1) * 8);
                cp16(dst + OFF_SB + bdst,  g_Bh + bsrcRow + kt + bcsel * 8);
            }
            CP_COMMIT();
        }

        const uint32_t sbase = sb + (uint32_t)(it & 3) * STAGE_BYTES;
#pragma unroll
        for (int ks = 0; ks < 2; ks++) {
            uint32_t a[2][4], b[2][4];
#pragma unroll
            for (int mt = 0; mt < 2; mt++)
                LDSM_X4(a[mt][0], a[mt][1], a[mt][2], a[mt][3],
                        sbase + OFF_SA + aoff[mt][ks]);
#pragma unroll
            for (int ng = 0; ng < 2; ng++)
                LDSM_X4(b[ng][0], b[ng][1], b[ng][2], b[ng][3],
                        sbase + OFF_SB + boff[ng][ks]);
#pragma unroll
            for (int mt = 0; mt < 2; mt++)
#pragma unroll
                for (int nt = 0; nt < 4; nt++) {
                    const int ng = nt >> 1, pr = (nt & 1) * 2;
                    mma_f16(acc[mt][nt], a[mt], b[ng][pr], b[ng][pr + 1]);
                }
        }
    }

    // ---- epilogue: scatter f32 (alpha already folded into B planes) ----
#pragma unroll
    for (int mt = 0; mt < 2; mt++)
#pragma unroll
        for (int h = 0; h < 2; h++) {
            const int r = tileM * 128 + wm * 32 + mt * 16 + (lane >> 2) + h * 8;
            const int b = r / d;
            const int m = r - b * d;
            float* orow = O + b * RSTRIDE + off + m;
#pragma unroll
            for (int nt = 0; nt < 4; nt++) {
                const int c0 = wn * 32 + nt * 8 + (lane & 3) * 2;
                orow[colOff[c0]]     = acc[mt][nt][h * 2 + 0];
                orow[colOff[c0 + 1]] = acc[mt][nt][h * 2 + 1];
            }
        }
}

// ---------------------------------------------------------------------------
// Launch: inputs: x (256,64,1771) f32, D (512,1771) f32, w (64,64,512) f32.
// ---------------------------------------------------------------------------
extern "C" void kernel_launch(void* const* d_in, const int* in_sizes, int n_in,
                              void* d_out, int out_size) {
    const float* x = (const float*)d_in[0];
    const float* D = (const float*)d_in[1];
    const float* w = (const float*)d_in[2];
    float* out = (float*)d_out;

    cudaFuncSetAttribute(so3_kernel, cudaFuncAttributeMaxDynamicSharedMemorySize, SO3_SMEM);

    xprep_kernel<<<dim3(BATCH, 11, 4), 256>>>(x);        // x -> A plane (fp16)
    psi_kernel<<<dim3(28, 64), 256>>>(w, D);             // W@D -> B plane (fp16, alpha folded)
    so3_kernel<<<3542, 256, SO3_SMEM>>>(out);
}

// round 10
// speedup vs baseline: 4.4448x; 1.2494x over previous
#include <cuda_runtime.h>
#include <cuda_fp16.h>
#include <cstdint>

// Problem constants
#define F_IN   64
#define F_OUT  64
#define IRREP  1771
#define NGRID  512
#define BATCH  256
#define RSTRIDE (F_OUT * IRREP)   // 113344

// fp16 planes.
// A_l: rows r=(b*d+m) [256d], cols k=(i*d+u) [64d]; base elem = 16384*c_off[l]
// B_l: rows n=(o*d+v) [64d],  cols k=(i*d+u) [64d]; base elem =  4096*c_off[l]
//      (scale/alpha folded into B)
#define AELEMS 29016064   // 16384*1771
#define BELEMS 7254016    // 4096*1771
__device__ __half g_Ah[AELEMS];
__device__ __half g_Bh[BELEMS];
// psi GEMM operands: W fp16 (4096 x 512, K-contig), D^T fp16 (1792 x 512, padded)
__device__ __half g_Wh[4096 * 512];
__device__ __half g_Dh[1792 * 512];

// stage-2 blocks per l = 2*d*d (tile 128x64); cumulative
__constant__ int c_cum2[12] = {0, 2, 20, 70, 168, 330, 572, 910, 1360, 1938, 2660, 3542};
// cumsum of d^2 (12 entries so [l+1] is always valid)
__constant__ int c_off12[12] = {0, 1, 10, 35, 84, 165, 286, 455, 680, 969, 1330, 1771};

// ---------------------------------------------------------------------------
// helpers
// ---------------------------------------------------------------------------
__device__ __forceinline__ uint32_t smem_u32(const void* p) {
    uint32_t a;
    asm("{ .reg .u64 t; cvta.to.shared.u64 t, %1; cvt.u32.u64 %0, t; }" : "=r"(a) : "l"(p));
    return a;
}

__device__ __forceinline__ void cp16(uint32_t dst, const void* src) {
    asm volatile("cp.async.cg.shared.global [%0], [%1], 16;"
                 :: "r"(dst), "l"((uint64_t)__cvta_generic_to_global(src)) : "memory");
}
#define CP_COMMIT() asm volatile("cp.async.commit_group;" ::: "memory")
#define CP_WAIT2()  asm volatile("cp.async.wait_group 2;" ::: "memory")

#define LDSM_X4(r0, r1, r2, r3, addr) \
    asm volatile("ldmatrix.sync.aligned.m8n8.x4.shared.b16 {%0,%1,%2,%3}, [%4];" \
                 : "=r"(r0), "=r"(r1), "=r"(r2), "=r"(r3) : "r"(addr))

__device__ __forceinline__ void mma_f16(float* c, const uint32_t* a, uint32_t b0, uint32_t b1) {
    asm volatile(
        "mma.sync.aligned.m16n8k16.row.col.f32.f16.f16.f32 "
        "{%0,%1,%2,%3}, {%4,%5,%6,%7}, {%8,%9}, {%0,%1,%2,%3};"
        : "+f"(c[0]), "+f"(c[1]), "+f"(c[2]), "+f"(c[3])
        : "r"(a[0]), "r"(a[1]), "r"(a[2]), "r"(a[3]), "r"(b0), "r"(b1));
}

__device__ __forceinline__ uint32_t packh2(float a, float b) {
    __half2 h = __floats2half2_rn(a, b);
    return *(uint32_t*)&h;
}

// ---------------------------------------------------------------------------
// Kernel W0: w (f_in, f_out, n_grid) f32 -> g_Wh fp16 (same layout).
// ---------------------------------------------------------------------------
__global__ __launch_bounds__(256) void wprep_kernel(const float* __restrict__ W) {
    const int idx = (blockIdx.x * 256 + threadIdx.x) * 8;   // 2M elems / 8
    float4 v0 = *(const float4*)(W + idx);
    float4 v1 = *(const float4*)(W + idx + 4);
    uint4 out;
    out.x = packh2(v0.x, v0.y);
    out.y = packh2(v0.z, v0.w);
    out.z = packh2(v1.x, v1.y);
    out.w = packh2(v1.z, v1.w);
    *(uint4*)(g_Wh + idx) = out;
}

// ---------------------------------------------------------------------------
// Kernel D0: D (512, 1771) f32 -> g_Dh fp16 transposed (1792, 512), zero pad.
// 32x32 tiles through smem. Block (32,8).
// FIX (R9 bug): the write must read the smem tile TRANSPOSED: sm[tx][r].
// ---------------------------------------------------------------------------
__global__ __launch_bounds__(256) void dprep_kernel(const float* __restrict__ D) {
    __shared__ float sm[32][33];
    const int c0 = blockIdx.x * 32;
    const int n0 = blockIdx.y * 32;
    const int tx = threadIdx.x;   // 0..31
    const int ty = threadIdx.y;   // 0..7

#pragma unroll
    for (int j = 0; j < 4; j++) {
        const int n = ty + j * 8;
        const int c = c0 + tx;
        sm[n][tx] = (c < IRREP) ? D[(n0 + n) * IRREP + c] : 0.0f;
    }
    __syncthreads();

#pragma unroll
    for (int j = 0; j < 4; j++) {
        const int r = ty + j * 8;             // c - c0
        // g_Dh[c][n] = D[n][c]  ->  value = sm[n_local=tx][c_local=r]
        g_Dh[(size_t)(c0 + r) * 512 + n0 + tx] = __float2half_rn(sm[tx][r]);
    }
}

// ---------------------------------------------------------------------------
// Kernel 0: xprep — x (B, F_IN, IRREP) f32 -> per-l fp16 A planes.
// Grid (b, l, ichunk). Phase 2 uses m-groups so all small-l threads work.
// ---------------------------------------------------------------------------
__global__ __launch_bounds__(256) void xprep_kernel(const float* __restrict__ X) {
    __shared__ float sm[16 * 441];
    const int b  = blockIdx.x;
    const int l  = blockIdx.y;
    const int ic = blockIdx.z;          // 0..3 (16 i's each)
    const int d  = 2 * l + 1;
    const int d2 = d * d;
    const int off = c_off12[l];
    const int Kl = 64 * d;
    const int tid = threadIdx.x;

    const float* xb = X + (size_t)b * RSTRIDE + (ic * 16) * IRREP + off;
#pragma unroll 4
    for (int ii = 0; ii < 16; ii++)
        for (int j = tid; j < d2; j += 256)
            sm[ii * d2 + j] = xb[ii * IRREP + j];
    __syncthreads();

    // Phase 2: thread = (pair p, m-group mg); pairs per chunk = 8d.
    const int ppc = 8 * d;
    const int nm  = 256 / ppc;          // m-groups
    if (tid < ppc * nm) {
        const int mg = tid / ppc;       // starting m
        const int p  = tid - mg * ppc;
        const int k0 = 2 * p;
        const int k1 = k0 + 1;
        const int i0 = k0 / d, u0 = k0 - i0 * d;
        const int i1 = k1 / d, u1 = k1 - i1 * d;
        const int s0 = i0 * d2 + u0 * d;
        const int s1 = i1 * d2 + u1 * d;

        const int Abase = 16384 * off;
        const int colBase = ic * 16 * d + k0;          // even -> 4B aligned
        int rowIdx = (b * d + mg) * Kl + colBase;
        for (int m = mg; m < d; m += nm, rowIdx += nm * Kl) {
            *(uint32_t*)(g_Ah + Abase + rowIdx) = packh2(sm[s0 + m], sm[s1 + m]);
        }
    }
}

// ---------------------------------------------------------------------------
// Kernel 1: psi GEMM on tensor cores.
//   psi[r=(i*64+o)][c] = (1/sqrt(512)) * sum_n Wh[r][n] * Dh[c][n]
//   M=4096 (32 tiles), N=1792 (28 tiles), K=512 (16 chunks of 32).
//   Epilogue scatters into g_Bh with scale*alpha folded.
// ---------------------------------------------------------------------------
#define STAGE_BYTES 12288
#define OFF_SA 0
#define OFF_SB 8192
#define SO3_SMEM (4 * STAGE_BYTES)

__global__ __launch_bounds__(256, 3) void psi_mma_kernel(void) {
    extern __shared__ __align__(1024) char dsm[];
    const uint32_t sb = smem_u32(dsm);

    const int tid  = threadIdx.x;
    const int wid  = tid >> 5;
    const int lane = tid & 31;
    const int wm = wid >> 1;
    const int wn = wid & 1;

    const int tileN = blockIdx.x;   // 0..27
    const int tileM = blockIdx.y;   // 0..31
    const int nIter = 16;           // K=512 / 32

    // cp.async geometry
    const int arow = tid & 127;
    const int acsel = (tid >> 7) * 2;
    const int asw = (arow >> 1) & 3;
    const uint32_t adst0 = (uint32_t)(arow * 64 + (((acsel + 0) ^ asw) << 4));
    const uint32_t adst1 = (uint32_t)(arow * 64 + (((acsel + 1) ^ asw) << 4));
    const __half* asrc = g_Wh + (size_t)(tileM * 128 + arow) * 512;

    const int brow = tid >> 2;
    const int bcsel = tid & 3;
    const uint32_t bdst = (uint32_t)(brow * 64 + ((bcsel ^ ((brow >> 1) & 3)) << 4));
    const __half* bsrc = g_Dh + (size_t)(tileN * 64 + brow) * 512;

    // ldmatrix geometry
    const int a_r0 = wm * 32 + (lane & 15);
    const int a_cbit = lane >> 4;
    const int b_r0 = wn * 32 + (lane & 7) + ((lane >> 4) << 3);
    const int b_cbit = (lane >> 3) & 1;

    uint32_t aoff[2][2], boff[2][2];
#pragma unroll
    for (int mt = 0; mt < 2; mt++) {
        const int row = a_r0 + mt * 16;
        const int sw = (row >> 1) & 3;
#pragma unroll
        for (int ks = 0; ks < 2; ks++)
            aoff[mt][ks] = (uint32_t)(row * 64 + (((ks * 2 + a_cbit) ^ sw) << 4));
    }
#pragma unroll
    for (int ng = 0; ng < 2; ng++) {
        const int row = b_r0 + ng * 16;
        const int sw = (row >> 1) & 3;
#pragma unroll
        for (int ks = 0; ks < 2; ks++)
            boff[ng][ks] = (uint32_t)(row * 64 + (((ks * 2 + b_cbit) ^ sw) << 4));
    }

#pragma unroll
    for (int s = 0; s < 3; s++) {
        const uint32_t dst = sb + (uint32_t)(s & 3) * STAGE_BYTES;
        const int kt = s * 32;
        cp16(dst + OFF_SA + adst0, asrc + kt + (acsel + 0) * 8);
        cp16(dst + OFF_SA + adst1, asrc + kt + (acsel + 1) * 8);
        cp16(dst + OFF_SB + bdst,  bsrc + kt + bcsel * 8);
        CP_COMMIT();
    }

    float acc[2][4][4] = {};

    for (int it = 0; it < nIter; ++it) {
        CP_WAIT2();
        __syncthreads();
        {
            const int s = it + 3;
            if (s < nIter) {
                const uint32_t dst = sb + (uint32_t)(s & 3) * STAGE_BYTES;
                const int kt = s * 32;
                cp16(dst + OFF_SA + adst0, asrc + kt + (acsel + 0) * 8);
                cp16(dst + OFF_SA + adst1, asrc + kt + (acsel + 1) * 8);
                cp16(dst + OFF_SB + bdst,  bsrc + kt + bcsel * 8);
            }
            CP_COMMIT();
        }

        const uint32_t sbase = sb + (uint32_t)(it & 3) * STAGE_BYTES;
#pragma unroll
        for (int ks = 0; ks < 2; ks++) {
            uint32_t a[2][4], b[2][4];
#pragma unroll
            for (int mt = 0; mt < 2; mt++)
                LDSM_X4(a[mt][0], a[mt][1], a[mt][2], a[mt][3],
                        sbase + OFF_SA + aoff[mt][ks]);
#pragma unroll
            for (int ng = 0; ng < 2; ng++)
                LDSM_X4(b[ng][0], b[ng][1], b[ng][2], b[ng][3],
                        sbase + OFF_SB + boff[ng][ks]);
#pragma unroll
            for (int mt = 0; mt < 2; mt++)
#pragma unroll
                for (int nt = 0; nt < 4; nt++) {
                    const int ng = nt >> 1, pr = (nt & 1) * 2;
                    mma_f16(acc[mt][nt], a[mt], b[ng][pr], b[ng][pr + 1]);
                }
        }
    }

    // Epilogue: scatter into B planes. c -> (l, u, v); r -> (i, o).
    const float scale = 0.04419417382415922f;  // 1/sqrt(512)
#pragma unroll
    for (int nt = 0; nt < 4; nt++) {
#pragma unroll
        for (int e = 0; e < 2; e++) {
            const int c = tileN * 64 + wn * 32 + nt * 8 + (lane & 3) * 2 + e;
            if (c >= IRREP) continue;
            int l = 0;
            while (c >= c_off12[l + 1]) ++l;
            const int d   = 2 * l + 1;
            const int off = c_off12[l];
            const int rel = c - off;
            const int u = rel / d;
            const int v = rel - u * d;
            const int Kl = 64 * d;
            const int Bbase = 4096 * off;
            const float sa = scale * rsqrtf(64.0f * (float)d);
#pragma unroll
            for (int mt = 0; mt < 2; mt++)
#pragma unroll
                for (int h = 0; h < 2; h++) {
                    const int r = tileM * 128 + wm * 32 + mt * 16 + (lane >> 2) + h * 8;
                    const int i = r >> 6;
                    const int o = r & 63;
                    g_Bh[Bbase + (o * d + v) * Kl + i * d + u] =
                        __float2half_rn(acc[mt][nt][h * 2 + e] * sa);
                }
        }
    }
}

// ---------------------------------------------------------------------------
// Kernel 2: so3 GEMM per l via mma.sync fp16 (unchanged from R7).
// ---------------------------------------------------------------------------
__global__ __launch_bounds__(256, 3) void so3_kernel(float* __restrict__ O) {
    extern __shared__ __align__(1024) char dsm[];
    __shared__ int colOff[64];
    const uint32_t sb = smem_u32(dsm);

    const int tid  = threadIdx.x;
    const int wid  = tid >> 5;
    const int lane = tid & 31;
    const int wm = wid >> 1;
    const int wn = wid & 1;

    const int bid = (int)gridDim.x - 1 - (int)blockIdx.x;
    int l = 0;
    while (bid >= c_cum2[l + 1]) ++l;
    const int d     = 2 * l + 1;
    const int off   = c_off12[l];
    const int loc   = bid - c_cum2[l];
    const int tileM = loc / d;
    const int tileN = loc - tileM * d;
    const int Kl    = 64 * d;
    const int nIter = 2 * d;

    const int Abase = 16384 * off;
    const int Bbase = 4096 * off;

    if (tid < 64) {
        const int gc = tileN * 64 + tid;
        const int o  = gc / d;
        const int v  = gc - o * d;
        colOff[tid] = o * IRREP + v * d;
    }

    const int arow = tid & 127;
    const int acsel = (tid >> 7) * 2;
    const int asw = (arow >> 1) & 3;
    const uint32_t adst0 = (uint32_t)(arow * 64 + (((acsel + 0) ^ asw) << 4));
    const uint32_t adst1 = (uint32_t)(arow * 64 + (((acsel + 1) ^ asw) << 4));
    const int asrcRow = Abase + (tileM * 128 + arow) * Kl;

    const int brow = tid >> 2;
    const int bcsel = tid & 3;
    const uint32_t bdst = (uint32_t)(brow * 64 + ((bcsel ^ ((brow >> 1) & 3)) << 4));
    const int bsrcRow = Bbase + (tileN * 64 + brow) * Kl;

    const int a_r0 = wm * 32 + (lane & 15);
    const int a_cbit = lane >> 4;
    const int b_r0 = wn * 32 + (lane & 7) + ((lane >> 4) << 3);
    const int b_cbit = (lane >> 3) & 1;

    uint32_t aoff[2][2], boff[2][2];
#pragma unroll
    for (int mt = 0; mt < 2; mt++) {
        const int row = a_r0 + mt * 16;
        const int sw = (row >> 1) & 3;
#pragma unroll
        for (int ks = 0; ks < 2; ks++)
            aoff[mt][ks] = (uint32_t)(row * 64 + (((ks * 2 + a_cbit) ^ sw) << 4));
    }
#pragma unroll
    for (int ng = 0; ng < 2; ng++) {
        const int row = b_r0 + ng * 16;
        const int sw = (row >> 1) & 3;
#pragma unroll
        for (int ks = 0; ks < 2; ks++)
            boff[ng][ks] = (uint32_t)(row * 64 + (((ks * 2 + b_cbit) ^ sw) << 4));
    }

#pragma unroll
    for (int s = 0; s < 3; s++) {
        if (s < nIter) {
            const uint32_t dst = sb + (uint32_t)(s & 3) * STAGE_BYTES;
            const int kt = s * 32;
            cp16(dst + OFF_SA + adst0, g_Ah + asrcRow + kt + (acsel + 0) * 8);
            cp16(dst + OFF_SA + adst1, g_Ah + asrcRow + kt + (acsel + 1) * 8);
            cp16(dst + OFF_SB + bdst,  g_Bh + bsrcRow + kt + bcsel * 8);
        }
        CP_COMMIT();
    }

    float acc[2][4][4] = {};

    for (int it = 0; it < nIter; ++it) {
        CP_WAIT2();
        __syncthreads();
        {
            const int s = it + 3;
            if (s < nIter) {
                const uint32_t dst = sb + (uint32_t)(s & 3) * STAGE_BYTES;
                const int kt = s * 32;
                cp16(dst + OFF_SA + adst0, g_Ah + asrcRow + kt + (acsel + 0) * 8);
                cp16(dst + OFF_SA + adst1, g_Ah + asrcRow + kt + (acsel + 1) * 8);
                cp16(dst + OFF_SB + bdst,  g_Bh + bsrcRow + kt + bcsel * 8);
            }
            CP_COMMIT();
        }

        const uint32_t sbase = sb + (uint32_t)(it & 3) * STAGE_BYTES;
#pragma unroll
        for (int ks = 0; ks < 2; ks++) {
            uint32_t a[2][4], b[2][4];
#pragma unroll
            for (int mt = 0; mt < 2; mt++)
                LDSM_X4(a[mt][0], a[mt][1], a[mt][2], a[mt][3],
                        sbase + OFF_SA + aoff[mt][ks]);
#pragma unroll
            for (int ng = 0; ng < 2; ng++)
                LDSM_X4(b[ng][0], b[ng][1], b[ng][2], b[ng][3],
                        sbase + OFF_SB + boff[ng][ks]);
#pragma unroll
            for (int mt = 0; mt < 2; mt++)
#pragma unroll
                for (int nt = 0; nt < 4; nt++) {
                    const int ng = nt >> 1, pr = (nt & 1) * 2;
                    mma_f16(acc[mt][nt], a[mt], b[ng][pr], b[ng][pr + 1]);
                }
        }
    }

#pragma unroll
    for (int mt = 0; mt < 2; mt++)
#pragma unroll
        for (int h = 0; h < 2; h++) {
            const int r = tileM * 128 + wm * 32 + mt * 16 + (lane >> 2) + h * 8;
            const int b = r / d;
            const int m = r - b * d;
            float* orow = O + b * RSTRIDE + off + m;
#pragma unroll
            for (int nt = 0; nt < 4; nt++) {
                const int c0 = wn * 32 + nt * 8 + (lane & 3) * 2;
                orow[colOff[c0]]     = acc[mt][nt][h * 2 + 0];
                orow[colOff[c0 + 1]] = acc[mt][nt][h * 2 + 1];
            }
        }
}

// ---------------------------------------------------------------------------
// Launch: inputs: x (256,64,1771) f32, D (512,1771) f32, w (64,64,512) f32.
// ---------------------------------------------------------------------------
extern "C" void kernel_launch(void* const* d_in, const int* in_sizes, int n_in,
                              void* d_out, int out_size) {
    const float* x = (const float*)d_in[0];
    const float* D = (const float*)d_in[1];
    const float* w = (const float*)d_in[2];
    float* out = (float*)d_out;

    cudaFuncSetAttribute(psi_mma_kernel, cudaFuncAttributeMaxDynamicSharedMemorySize, SO3_SMEM);
    cudaFuncSetAttribute(so3_kernel,     cudaFuncAttributeMaxDynamicSharedMemorySize, SO3_SMEM);

    wprep_kernel<<<1024, 256>>>(w);                      // w -> fp16
    dprep_kernel<<<dim3(56, 16), dim3(32, 8)>>>(D);      // D -> fp16 transposed+padded
    xprep_kernel<<<dim3(BATCH, 11, 4), 256>>>(x);        // x -> A plane (fp16)
    psi_mma_kernel<<<dim3(28, 32), 256, SO3_SMEM>>>();   // W@D -> B plane (tensor cores)
    so3_kernel<<<3542, 256, SO3_SMEM>>>(out);
}